// round 15
// baseline (speedup 1.0000x reference)
#include <cuda_runtime.h>
#include <cuda_bf16.h>
#include <math.h>

#define T_STEPS 4096
#define FD 32
#define SD 16
#define HD 48
#define VOCAB 50257

#define VBLOCK 2048
#define NVB 25
#define TT 32
#define NTB 128
#define TILES (NVB * NTB)
#define NBLK 148

typedef unsigned long long ull;

// ---------------- scratch ----------------
__device__ float g_xg[T_STEPS * FD];   // 0.5 * (W_gate_x @ x)
__device__ float g_xp[T_STEPS * FD];   // 0.5 * (W_x_proj @ x)
__device__ float g_xd[T_STEPS * FD];   // W_x_fast @ x
__device__ float g_h [T_STEPS * HD];
__device__ float g_partial[NVB * T_STEPS];
__device__ int g_prog;
__device__ int g_tile;
__device__ int g_done;

// ---------------- helpers ----------------
#define FMA2(acc, a, b) asm("fma.rn.f32x2 %0, %1, %2, %0;" : "+l"(acc) : "l"(a), "l"(b))
#define ADD2(d, a, b)   asm("add.rn.f32x2 %0, %1, %2;"     : "=l"(d)   : "l"(a), "l"(b))
#define WFENCE()        asm volatile("" ::: "memory")
// producer/consumer named barriers — STRICT one-arrive/one-sync per step
// (R12/R14 showed any cadence change deadlocks; do not touch)
#define ARRIVE_A() asm volatile("bar.arrive 1, 64;" ::: "memory")
#define SYNC_A()   asm volatile("bar.sync 1, 64;"   ::: "memory")
#define ARRIVE_B() asm volatile("bar.arrive 2, 64;" ::: "memory")
#define SYNC_B()   asm volatile("bar.sync 2, 64;"   ::: "memory")

__device__ __forceinline__ ull pack2(float lo, float hi) {
    ull r; asm("mov.b64 %0, {%1, %2};" : "=l"(r) : "f"(lo), "f"(hi)); return r;
}
__device__ __forceinline__ float redu2(ull a0, ull a1) {
    ull s; ADD2(s, a0, a1);
    float lo, hi; asm("mov.b64 {%0, %1}, %2;" : "=f"(lo), "=f"(hi) : "l"(s));
    return lo + hi;
}
__device__ __forceinline__ float redu4(ull a0, ull a1, ull a2, ull a3) {
    ull s0, s1;
    ADD2(s0, a0, a1); ADD2(s1, a2, a3); ADD2(s0, s0, s1);
    float lo, hi; asm("mov.b64 {%0, %1}, %2;" : "=f"(lo), "=f"(hi) : "l"(s0));
    return lo + hi;
}
__device__ __forceinline__ float tanh_f(float x) {
    float r; asm("tanh.approx.f32 %0, %1;" : "=f"(r) : "f"(x)); return r;
}
__device__ __forceinline__ void publish(int v) {
    asm volatile("st.release.gpu.b32 [%0], %1;" :: "l"(&g_prog), "r"(v) : "memory");
}
__device__ __forceinline__ int load_prog() {
    int v; asm volatile("ld.acquire.gpu.b32 %0, [%1];" : "=r"(v) : "l"(&g_prog) : "memory");
    return v;
}

// 2-accumulator dots, bias packed into accumulator init (proven fastest)
__device__ __forceinline__ float dot32i(const ull* w2, const ulonglong2* h2, ull init) {
    ull a0 = init, a1 = 0;
#pragma unroll
    for (int m = 0; m < 8; m++) {
        ulonglong2 pp = h2[m];
        FMA2(a0, w2[2 * m], pp.x);
        FMA2(a1, w2[2 * m + 1], pp.y);
    }
    return redu2(a0, a1);
}
__device__ __forceinline__ float dot16i(const ull* w2, const ulonglong2* h2, ull init) {
    ull a0 = init, a1 = 0;
#pragma unroll
    for (int m = 0; m < 4; m++) {
        ulonglong2 pp = h2[m];
        FMA2(a0, w2[2 * m], pp.x);
        FMA2(a1, w2[2 * m + 1], pp.y);
    }
    return redu2(a0, a1);
}
__device__ __forceinline__ float dot32(const ull* w2, const ulonglong2* h2) {
    ull a0 = 0, a1 = 0, a2 = 0, a3 = 0;
#pragma unroll
    for (int m = 0; m < 8; m++) {
        ulonglong2 pp = h2[m];
        if (m & 1) { FMA2(a2, w2[2 * m], pp.x); FMA2(a3, w2[2 * m + 1], pp.y); }
        else       { FMA2(a0, w2[2 * m], pp.x); FMA2(a1, w2[2 * m + 1], pp.y); }
    }
    return redu4(a0, a1, a2, a3);
}

// ============================================================
// K1: precompute drives (xg, xp pre-halved for sigmoid folding)
// ============================================================
__global__ void precompute_kernel(const int* __restrict__ tok,
                                  const float* __restrict__ embed,
                                  const float* __restrict__ Wgx,
                                  const float* __restrict__ Wxp,
                                  const float* __restrict__ Wxf)
{
    int t = blockIdx.x;
    int i = threadIdx.x;
    if (t == 0 && i == 0) { g_prog = 0; g_tile = 0; g_done = 0; }
    __shared__ __align__(16) float xs[FD];
    int tk = tok[t];
    xs[i] = embed[(size_t)tk * FD + i];
    __syncwarp();
    const ulonglong2* x2 = (const ulonglong2*)xs;
    const ull* pg = (const ull*)(Wgx + (size_t)i * FD);
    const ull* pp = (const ull*)(Wxp + (size_t)i * FD);
    const ull* pf = (const ull*)(Wxf + (size_t)i * FD);
    ull wg[16], wp[16], wf[16];
#pragma unroll
    for (int q = 0; q < 16; q++) { wg[q] = pg[q]; wp[q] = pp[q]; wf[q] = pf[q]; }
    g_xg[t * FD + i] = 0.5f * dot32(wg, x2);
    g_xp[t * FD + i] = 0.5f * dot32(wp, x2);
    g_xd[t * FD + i] = dot32(wf, x2);
}

// ---------------- block-0 shared state ----------------
struct ScanSmem {
    float hfin[2][FD];   // final h_fast per step parity (warp0 writes)
    float wk0[FD];       // warp0-private relax buffers
    float wk1[FD];
    float sdelta[FD];    // h_slow increment (warp1-private)
    float sdr[FD];       // sdrive vector (warp1 -> warp0)
};

// ============================================================
// warp0: gate + relax. SYNC_B moved right after the gate STS so the
// sdr LDS hides under the relax1 dot; relax2 dot init folds
// 0.75*r1 + 0.25*cd + sdr (no post-dot adds). One B-sync per step.
// ============================================================
__device__ void scan_warp0(int i, ScanSmem* S,
    const float* __restrict__ Wgh, const float* __restrict__ bgh_p,
    const float* __restrict__ Wff, const float* __restrict__ bff_p)
{
    ull wghH2[16], wff2[16];
#pragma unroll
    for (int q = 0; q < 16; q++)
        wghH2[q] = pack2(0.5f * Wgh[i * FD + 2 * q], 0.5f * Wgh[i * FD + 2 * q + 1]);
    {
        const ull* p1 = (const ull*)(Wff + (size_t)i * FD);
#pragma unroll
        for (int q = 0; q < 16; q++) wff2[q] = p1[q];
    }
    float bghH = 0.5f * bgh_p[i];
    float bff  = bff_p[i];

    S->hfin[0][i] = 0.f; S->hfin[1][i] = 0.f;
    float hf = 0.f;
    WFENCE();
    ARRIVE_A();                      // prime: h_fast(-1)=0 published

    float cg[4], cp[4], cd[4];
#pragma unroll
    for (int k = 0; k < 4; k++) {
        cg[k] = g_xg[k * FD + i] + bghH;
        cp[k] = g_xp[k * FD + i];
        cd[k] = g_xd[k * FD + i] + bff;
    }

    for (int tg = 0; tg < T_STEPS / 4; tg++) {
        float ng[4], np[4], nd[4];
        if (tg + 1 < T_STEPS / 4) {
            int tb = (4 * tg + 4) * FD + i;
#pragma unroll
            for (int k = 0; k < 4; k++) {
                ng[k] = g_xg[tb + k * FD] + bghH;
                np[k] = g_xp[tb + k * FD];
                nd[k] = g_xd[tb + k * FD] + bff;
            }
        } else {
#pragma unroll
            for (int k = 0; k < 4; k++) { ng[k] = 0.f; np[k] = 0.f; nd[k] = 0.f; }
        }

#pragma unroll
        for (int k = 0; k < 4; k++) {
            int t = 4 * tg + k;
            const ulonglong2* hp2 = (const ulonglong2*)S->hfin[(t + 1) & 1];

            // gate stage (operands warp0-local)
            float gd = dot32i(wghH2, hp2, pack2(cg[k], 0.f));
            float tv = tanh_f(gd);
            float base = hf + cp[k];
            hf = fmaf(cp[k], tv, base);              // h1
            S->wk0[i] = hf;
            WFENCE();

            SYNC_B();                                // warp1 arrived ~40cy ago
            float sdr = S->sdr[i];                   // LDS hides under r1 dot

            float r1 = dot32i(wff2, (const ulonglong2*)S->wk0, pack2(cd[k], 0.f));
            float hf75 = 0.75f * hf;
            float i75 = fmaf(0.75f, r1, 0.25f * cd[k]);  // off-chain (tanh window)
            float t1 = tanh_f(r1 + sdr);
            hf = fmaf(0.25f, t1, hf75);              // h2
            float q = 0.25f * t1;
            S->wk1[i] = q;                           // exchange 0.25*tanh(u1)
            float init2 = i75 + sdr;                 // 0.75*Wff@h1 + cd + sdr
            float hf75b = 0.75f * hf;
            WFENCE();
            float u2 = dot32i(wff2, (const ulonglong2*)S->wk1, pack2(init2, 0.f));
            float t2 = tanh_f(u2);                   // no post-dot adds
            hf = fmaf(0.25f, t2, hf75b);             // h3 = hfin(t)
            S->hfin[t & 1][i] = hf;
            WFENCE();
            ARRIVE_A();                              // h_fast(t) published
        }
#pragma unroll
        for (int k = 0; k < 4; k++) { cg[k] = ng[k]; cp[k] = np[k]; cd[k] = nd[k]; }
    }
}

// ============================================================
// warp1: R13-exact. Posts previous iteration's register-resident sdr
// immediately after SYNC_A, then does all heavy work overlapped.
// Step t's relax drive = Wfs @ h_slow(t-2) (validated: rel_err 8.8e-8).
// ============================================================
__device__ void scan_warp1(int i, ScanSmem* S,
    const float* __restrict__ Wsgf, const float* __restrict__ bsgf,
    const float* __restrict__ Wsgs,
    const float* __restrict__ Wss, const float* __restrict__ bss,
    const float* __restrict__ Wsf, const float* __restrict__ Wfs)
{
    ull ws2[24], wfs2[8];
    float bs;
    if (i < SD) {
        // slow-gate rows pre-halved (sigmoid fold)
#pragma unroll
        for (int q = 0; q < 16; q++)
            ws2[q] = pack2(0.5f * Wsgf[i * FD + 2 * q], 0.5f * Wsgf[i * FD + 2 * q + 1]);
#pragma unroll
        for (int q = 0; q < 8; q++)
            ws2[16 + q] = pack2(0.5f * Wsgs[i * SD + 2 * q], 0.5f * Wsgs[i * SD + 2 * q + 1]);
        bs = 0.5f * bsgf[i];
    } else {
        const ull* pa = (const ull*)(Wsf + (size_t)(i - SD) * FD);
        const ull* pb = (const ull*)(Wss + (size_t)(i - SD) * SD);
#pragma unroll
        for (int q = 0; q < 16; q++) ws2[q] = pa[q];
#pragma unroll
        for (int q = 0; q < 8; q++) ws2[16 + q] = pb[q];
        bs = bss[i - SD];
    }
    {
        const ull* p2 = (const ull*)(Wfs + (size_t)i * SD);
#pragma unroll
        for (int q = 0; q < 8; q++) wfs2[q] = p2[q];
    }
    S->sdelta[i] = 0.f;
    S->sdr[i] = 0.f;          // sdr(0) = 0
    float hs = 0.f;           // lanes<16 meaningful
    float sdr_acc = 0.f;      // Wfs @ h_slow, register-resident
    float ssb_acc = bs;       // bias + slow-block @ h_slow accumulator
    WFENCE();

    for (int t = 0; t < T_STEPS; t++) {
        SYNC_A();                                      // h_fast(t-1) ready

        if (t > 0) {
            S->sdr[i] = sdr_acc;                       // sdr(t) (from iter t-1)
            WFENCE();
            ARRIVE_B();                                // warp0 unblocked ASAP
            // ---- all heavy work overlaps warp0's step t ----
            const float* hp = S->hfin[(t + 1) & 1];
            float hfl = hp[i];
            float sacc = dot32i(ws2, (const ulonglong2*)hp, pack2(ssb_acc, 0.f));
            float val = tanh_f(sacc);
            if (i < SD) val = fmaf(0.5f, val, 0.5f);   // sigmoid (halved domain)
            float prt = __shfl_xor_sync(0xffffffffu, val, 16);
            float delta = 0.02f * val * (prt - hs);    // lanes>=16: junk (pad)
            S->sdelta[i] = delta;
            WFENCE();
            float dsdr = dot16i(wfs2, (const ulonglong2*)S->sdelta, pack2(0.f, 0.f));
            sdr_acc += dsdr;                           // -> sdr(t+1)
            float dssb = dot16i(ws2 + 16, (const ulonglong2*)S->sdelta, pack2(0.f, 0.f));
            ssb_acc += dssb;
            if (i < SD) hs += delta;                   // exact h_slow(t-1)
            g_h[(t - 1) * HD + i] = hfl;
            if (i < SD) g_h[(t - 1) * HD + FD + i] = hs;
            if (((t & 31) == 0) && i == 0) publish(t);
        } else {
            ARRIVE_B();                                // sdr(0)=0 pre-zeroed
        }
    }

    // tail: exact slow update + row T-1
    {
        SYNC_A();
        const float* hp = S->hfin[(T_STEPS - 1) & 1];
        float sacc = dot32i(ws2, (const ulonglong2*)hp, pack2(ssb_acc, 0.f));
        float val = tanh_f(sacc);
        if (i < SD) val = fmaf(0.5f, val, 0.5f);
        float prt = __shfl_xor_sync(0xffffffffu, val, 16);
        float hsn = fmaf(0.02f * val, prt - hs, hs);
        float hfl = hp[i];
        g_h[(T_STEPS - 1) * HD + i] = hfl;
        if (i < SD) g_h[(T_STEPS - 1) * HD + FD + i] = hsn;
        __syncwarp();
        if (i == 0) publish(T_STEPS);
    }
}

// ============================================================
// head tile — one (vb, tb) partial-sumexp tile (256 threads)
// ============================================================
__device__ void head_tile(int vb, int tb,
                          const float* __restrict__ Wout,
                          const float* __restrict__ bout)
{
    int tid = threadIdx.x;
    __shared__ __align__(16) float hsh[TT][HD];
    const float* hsrc = g_h + (size_t)tb * TT * HD;
    for (int k = tid; k < TT * HD; k += 256)
        ((float*)hsh)[k] = hsrc[k];
    __syncthreads();

    float acc[TT];
#pragma unroll
    for (int q = 0; q < TT; q++) acc[q] = 0.f;

    for (int vi = 0; vi < VBLOCK / 256; vi++) {
        int v = vb * VBLOCK + vi * 256 + tid;
        if (v < VOCAB) {
            ull w2[24];
            const ulonglong2* wp = (const ulonglong2*)(Wout + (size_t)v * HD);
#pragma unroll
            for (int q = 0; q < 12; q++) {
                ulonglong2 t4 = wp[q]; w2[2 * q] = t4.x; w2[2 * q + 1] = t4.y;
            }
            ull bo2 = pack2(bout[v], 0.f);
#pragma unroll 2
            for (int tt = 0; tt < TT; tt++) {
                const ulonglong2* hp = (const ulonglong2*)hsh[tt];
                ull a0 = bo2, a1 = 0, a2 = 0, a3 = 0;
#pragma unroll
                for (int m = 0; m < 12; m++) {
                    ulonglong2 pp = hp[m];
                    if (m & 1) { FMA2(a2, w2[2 * m], pp.x); FMA2(a3, w2[2 * m + 1], pp.y); }
                    else       { FMA2(a0, w2[2 * m], pp.x); FMA2(a1, w2[2 * m + 1], pp.y); }
                }
                acc[tt] += __expf(redu4(a0, a1, a2, a3));
            }
        }
    }

    __shared__ float swarp[8][TT];
    int lane = tid & 31, wrp = tid >> 5;
#pragma unroll
    for (int tt = 0; tt < TT; tt++) {
        float v = acc[tt];
        v += __shfl_xor_sync(0xffffffff, v, 16);
        v += __shfl_xor_sync(0xffffffff, v, 8);
        v += __shfl_xor_sync(0xffffffff, v, 4);
        v += __shfl_xor_sync(0xffffffff, v, 2);
        v += __shfl_xor_sync(0xffffffff, v, 1);
        if (lane == 0) swarp[wrp][tt] = v;
    }
    __syncthreads();
    if (tid < TT) {
        float s = 0.f;
#pragma unroll
        for (int q = 0; q < 8; q++) s += swarp[q][tid];
        g_partial[(size_t)vb * T_STEPS + tb * TT + tid] = s;
    }
    __syncthreads();
}

// ============================================================
// finale — NLL + mean
// ============================================================
__device__ void finale(const int* __restrict__ tok,
                       const float* __restrict__ Wout,
                       const float* __restrict__ bout,
                       float* __restrict__ out)
{
    int tid = threadIdx.x;
    float local = 0.f;
    for (int t = tid; t < T_STEPS; t += 256) {
        float s = 0.f;
#pragma unroll
        for (int vb = 0; vb < NVB; vb++) s += g_partial[(size_t)vb * T_STEPS + t];
        int tgt = tok[t + 1];
        const float* wr = Wout + (size_t)tgt * HD;
        const float* hr = g_h + t * HD;
        float a = bout[tgt];
#pragma unroll
        for (int k = 0; k < HD; k++) a = fmaf(wr[k], hr[k], a);
        local += logf(s) - a;
    }
    __shared__ float red[256];
    red[tid] = local;
    __syncthreads();
    for (int st = 128; st > 0; st >>= 1) {
        if (tid < st) red[tid] += red[tid + st];
        __syncthreads();
    }
    if (tid == 0) out[0] = red[0] / (float)T_STEPS;
}

// ============================================================
// fused persistent kernel
// ============================================================
__global__ void __launch_bounds__(256, 1) fused_kernel(
    const int* __restrict__ tok,
    const float* __restrict__ Wgh, const float* __restrict__ bgh,
    const float* __restrict__ Wff, const float* __restrict__ bff,
    const float* __restrict__ Wfs,
    const float* __restrict__ Wsgf, const float* __restrict__ bsgf,
    const float* __restrict__ Wsgs,
    const float* __restrict__ Wss, const float* __restrict__ bss,
    const float* __restrict__ Wsf,
    const float* __restrict__ Wout, const float* __restrict__ bout,
    float* __restrict__ out)
{
    int tid = threadIdx.x;

    if (blockIdx.x == 0) {
        __shared__ __align__(16) ScanSmem S;
        int lane = tid & 31;
        if (tid < 32)
            scan_warp0(lane, &S, Wgh, bgh, Wff, bff);
        else if (tid < 64)
            scan_warp1(lane, &S, Wsgf, bsgf, Wsgs, Wss, bss, Wsf, Wfs);
        return;
    }

    __shared__ int s_tile;
    __shared__ int s_flag;
    for (;;) {
        if (tid == 0) s_tile = atomicAdd(&g_tile, 1);
        __syncthreads();
        int tile = s_tile;
        if (tile >= TILES) break;
        int tb = tile / NVB;
        int vb = tile - tb * NVB;

        if (tid == 0) {
            int need = (tb + 1) * TT;
            while (load_prog() < need) __nanosleep(64);
        }
        __syncthreads();

        head_tile(vb, tb, Wout, bout);

        if (tid == 0) {
            __threadfence();
            int d = atomicAdd(&g_done, 1);
            s_flag = (d == TILES - 1);
        }
        __syncthreads();
        if (s_flag) {
            __threadfence();
            finale(tok, Wout, bout, out);
        }
        __syncthreads();
    }
}

// ============================================================
extern "C" void kernel_launch(void* const* d_in, const int* in_sizes, int n_in,
                              void* d_out, int out_size)
{
    const int*   tok   = (const int*)  d_in[0];
    const float* embed = (const float*)d_in[1];
    const float* Wgh   = (const float*)d_in[2];
    const float* bgh   = (const float*)d_in[3];
    const float* Wgx   = (const float*)d_in[4];
    const float* Wxp   = (const float*)d_in[5];
    const float* Wff   = (const float*)d_in[6];
    const float* bff   = (const float*)d_in[7];
    const float* Wfs   = (const float*)d_in[8];
    const float* Wxf   = (const float*)d_in[9];
    const float* Wsgf  = (const float*)d_in[10];
    const float* bsgf  = (const float*)d_in[11];
    const float* Wsgs  = (const float*)d_in[12];
    const float* Wss   = (const float*)d_in[13];
    const float* bss   = (const float*)d_in[14];
    const float* Wsf   = (const float*)d_in[15];
    const float* Wout  = (const float*)d_in[16];
    const float* bout  = (const float*)d_in[17];

    precompute_kernel<<<T_STEPS, 32>>>(tok, embed, Wgx, Wxp, Wxf);
    fused_kernel<<<NBLK, 256>>>(tok, Wgh, bgh, Wff, bff, Wfs,
                                Wsgf, bsgf, Wsgs, Wss, bss, Wsf,
                                Wout, bout, (float*)d_out);
}

// round 16
// speedup vs baseline: 1.1989x; 1.1989x over previous
#include <cuda_runtime.h>
#include <cuda_bf16.h>
#include <math.h>

#define T_STEPS 4096
#define FD 32
#define SD 16
#define HD 48
#define VOCAB 50257

#define VBLOCK 2048
#define NVB 25
#define TT 32
#define NTB 128
#define TILES (NVB * NTB)
#define NBLK 148

typedef unsigned long long ull;

// ---------------- scratch ----------------
__device__ float g_xg[T_STEPS * FD];   // 0.5 * (W_gate_x @ x)
__device__ float g_xp[T_STEPS * FD];   // 0.5 * (W_x_proj @ x)
__device__ float g_xd[T_STEPS * FD];   // W_x_fast @ x
__device__ float g_h [T_STEPS * HD];
__device__ float g_partial[NVB * T_STEPS];
__device__ int g_prog;
__device__ int g_tile;
__device__ int g_done;

// ---------------- helpers ----------------
#define FMA2(acc, a, b) asm("fma.rn.f32x2 %0, %1, %2, %0;" : "+l"(acc) : "l"(a), "l"(b))
#define ADD2(d, a, b)   asm("add.rn.f32x2 %0, %1, %2;"     : "=l"(d)   : "l"(a), "l"(b))
#define WFENCE()        asm volatile("" ::: "memory")
// producer/consumer named barriers — STRICT one-arrive/one-sync per step,
// SYNC_B placed AFTER the relax1 dot issue (R13-proven; R15 showed moving
// it earlier exposes the release latency)
#define ARRIVE_A() asm volatile("bar.arrive 1, 64;" ::: "memory")
#define SYNC_A()   asm volatile("bar.sync 1, 64;"   ::: "memory")
#define ARRIVE_B() asm volatile("bar.arrive 2, 64;" ::: "memory")
#define SYNC_B()   asm volatile("bar.sync 2, 64;"   ::: "memory")

__device__ __forceinline__ ull pack2(float lo, float hi) {
    ull r; asm("mov.b64 %0, {%1, %2};" : "=l"(r) : "f"(lo), "f"(hi)); return r;
}
__device__ __forceinline__ float redu2(ull a0, ull a1) {
    ull s; ADD2(s, a0, a1);
    float lo, hi; asm("mov.b64 {%0, %1}, %2;" : "=f"(lo), "=f"(hi) : "l"(s));
    return lo + hi;
}
__device__ __forceinline__ float redu4(ull a0, ull a1, ull a2, ull a3) {
    ull s0, s1;
    ADD2(s0, a0, a1); ADD2(s1, a2, a3); ADD2(s0, s0, s1);
    float lo, hi; asm("mov.b64 {%0, %1}, %2;" : "=f"(lo), "=f"(hi) : "l"(s0));
    return lo + hi;
}
__device__ __forceinline__ float tanh_f(float x) {
    float r; asm("tanh.approx.f32 %0, %1;" : "=f"(r) : "f"(x)); return r;
}
__device__ __forceinline__ void publish(int v) {
    asm volatile("st.release.gpu.b32 [%0], %1;" :: "l"(&g_prog), "r"(v) : "memory");
}
__device__ __forceinline__ int load_prog() {
    int v; asm volatile("ld.acquire.gpu.b32 %0, [%1];" : "=r"(v) : "l"(&g_prog) : "memory");
    return v;
}

// 2-accumulator dots, bias packed into accumulator init (proven fastest)
__device__ __forceinline__ float dot32i(const ull* w2, const ulonglong2* h2, ull init) {
    ull a0 = init, a1 = 0;
#pragma unroll
    for (int m = 0; m < 8; m++) {
        ulonglong2 pp = h2[m];
        FMA2(a0, w2[2 * m], pp.x);
        FMA2(a1, w2[2 * m + 1], pp.y);
    }
    return redu2(a0, a1);
}
__device__ __forceinline__ float dot16i(const ull* w2, const ulonglong2* h2, ull init) {
    ull a0 = init, a1 = 0;
#pragma unroll
    for (int m = 0; m < 4; m++) {
        ulonglong2 pp = h2[m];
        FMA2(a0, w2[2 * m], pp.x);
        FMA2(a1, w2[2 * m + 1], pp.y);
    }
    return redu2(a0, a1);
}
__device__ __forceinline__ float dot32(const ull* w2, const ulonglong2* h2) {
    ull a0 = 0, a1 = 0, a2 = 0, a3 = 0;
#pragma unroll
    for (int m = 0; m < 8; m++) {
        ulonglong2 pp = h2[m];
        if (m & 1) { FMA2(a2, w2[2 * m], pp.x); FMA2(a3, w2[2 * m + 1], pp.y); }
        else       { FMA2(a0, w2[2 * m], pp.x); FMA2(a1, w2[2 * m + 1], pp.y); }
    }
    return redu4(a0, a1, a2, a3);
}

// ============================================================
// K1: precompute drives (xg, xp pre-halved for sigmoid folding)
// ============================================================
__global__ void precompute_kernel(const int* __restrict__ tok,
                                  const float* __restrict__ embed,
                                  const float* __restrict__ Wgx,
                                  const float* __restrict__ Wxp,
                                  const float* __restrict__ Wxf)
{
    int t = blockIdx.x;
    int i = threadIdx.x;
    if (t == 0 && i == 0) { g_prog = 0; g_tile = 0; g_done = 0; }
    __shared__ __align__(16) float xs[FD];
    int tk = tok[t];
    xs[i] = embed[(size_t)tk * FD + i];
    __syncwarp();
    const ulonglong2* x2 = (const ulonglong2*)xs;
    const ull* pg = (const ull*)(Wgx + (size_t)i * FD);
    const ull* pp = (const ull*)(Wxp + (size_t)i * FD);
    const ull* pf = (const ull*)(Wxf + (size_t)i * FD);
    ull wg[16], wp[16], wf[16];
#pragma unroll
    for (int q = 0; q < 16; q++) { wg[q] = pg[q]; wp[q] = pp[q]; wf[q] = pf[q]; }
    g_xg[t * FD + i] = 0.5f * dot32(wg, x2);
    g_xp[t * FD + i] = 0.5f * dot32(wp, x2);
    g_xd[t * FD + i] = dot32(wf, x2);
}

// ---------------- block-0 shared state ----------------
struct ScanSmem {
    float hfin[2][FD];   // final h_fast per step parity (warp0 writes)
    float wk0[FD];       // warp0-private relax buffers
    float wk1[FD];
    float sdelta[FD];    // h_slow increment (warp1-private)
    float sdr[FD];       // sdrive vector (warp1 -> warp0)
};

// ============================================================
// warp0: gate + relax — R13 structure; only change: relax2 dot init
// folds 0.75*r1 + 0.25*cd + sdr (post-dot +sdr removed from chain).
// ============================================================
__device__ void scan_warp0(int i, ScanSmem* S,
    const float* __restrict__ Wgh, const float* __restrict__ bgh_p,
    const float* __restrict__ Wff, const float* __restrict__ bff_p)
{
    ull wghH2[16], wff2[16];
#pragma unroll
    for (int q = 0; q < 16; q++)
        wghH2[q] = pack2(0.5f * Wgh[i * FD + 2 * q], 0.5f * Wgh[i * FD + 2 * q + 1]);
    {
        const ull* p1 = (const ull*)(Wff + (size_t)i * FD);
#pragma unroll
        for (int q = 0; q < 16; q++) wff2[q] = p1[q];
    }
    float bghH = 0.5f * bgh_p[i];
    float bff  = bff_p[i];

    S->hfin[0][i] = 0.f; S->hfin[1][i] = 0.f;
    float hf = 0.f;
    WFENCE();
    ARRIVE_A();                      // prime: h_fast(-1)=0 published

    float cg[4], cp[4], cd[4];
#pragma unroll
    for (int k = 0; k < 4; k++) {
        cg[k] = g_xg[k * FD + i] + bghH;
        cp[k] = g_xp[k * FD + i];
        cd[k] = g_xd[k * FD + i] + bff;
    }

    for (int tg = 0; tg < T_STEPS / 4; tg++) {
        float ng[4], np[4], nd[4];
        if (tg + 1 < T_STEPS / 4) {
            int tb = (4 * tg + 4) * FD + i;
#pragma unroll
            for (int k = 0; k < 4; k++) {
                ng[k] = g_xg[tb + k * FD] + bghH;
                np[k] = g_xp[tb + k * FD];
                nd[k] = g_xd[tb + k * FD] + bff;
            }
        } else {
#pragma unroll
            for (int k = 0; k < 4; k++) { ng[k] = 0.f; np[k] = 0.f; nd[k] = 0.f; }
        }

#pragma unroll
        for (int k = 0; k < 4; k++) {
            int t = 4 * tg + k;
            const ulonglong2* hp2 = (const ulonglong2*)S->hfin[(t + 1) & 1];

            // gate stage (operands warp0-local)
            float gd = dot32i(wghH2, hp2, pack2(cg[k], 0.f));
            float tv = tanh_f(gd);
            float base = hf + cp[k];
            hf = fmaf(cp[k], tv, base);              // h1
            S->wk0[i] = hf;
            WFENCE();
            // relax1 dot issued before the wait; completes during it
            float r1 = dot32i(wff2, (const ulonglong2*)S->wk0, pack2(cd[k], 0.f));
            float hf75 = 0.75f * hf;
            float i75 = fmaf(0.75f, r1, 0.25f * cd[k]);  // off-chain precompute

            SYNC_B();                                // sdr(t) ready (near-zero wait)

            float sdr = S->sdr[i];
            float t1 = tanh_f(r1 + sdr);
            hf = fmaf(0.25f, t1, hf75);              // h2
            float q = 0.25f * t1;
            S->wk1[i] = q;                           // exchange 0.25*tanh(u1)
            float init2 = i75 + sdr;                 // 0.75*Wff@h1 + cd + sdr (in tanh shadow)
            float hf75b = 0.75f * hf;
            WFENCE();
            float u2 = dot32i(wff2, (const ulonglong2*)S->wk1, pack2(init2, 0.f));
            float t2 = tanh_f(u2);                   // no post-dot adds
            hf = fmaf(0.25f, t2, hf75b);             // h3 = hfin(t)
            S->hfin[t & 1][i] = hf;
            WFENCE();
            ARRIVE_A();                              // h_fast(t) published
        }
#pragma unroll
        for (int k = 0; k < 4; k++) { cg[k] = ng[k]; cp[k] = np[k]; cd[k] = nd[k]; }
    }
}

// ============================================================
// warp1: R13-exact. Posts previous iteration's register-resident sdr
// immediately after SYNC_A, then does all heavy work overlapped.
// Step t's relax drive = Wfs @ h_slow(t-2) (validated: rel_err 8.8e-8).
// ============================================================
__device__ void scan_warp1(int i, ScanSmem* S,
    const float* __restrict__ Wsgf, const float* __restrict__ bsgf,
    const float* __restrict__ Wsgs,
    const float* __restrict__ Wss, const float* __restrict__ bss,
    const float* __restrict__ Wsf, const float* __restrict__ Wfs)
{
    ull ws2[24], wfs2[8];
    float bs;
    if (i < SD) {
        // slow-gate rows pre-halved (sigmoid fold)
#pragma unroll
        for (int q = 0; q < 16; q++)
            ws2[q] = pack2(0.5f * Wsgf[i * FD + 2 * q], 0.5f * Wsgf[i * FD + 2 * q + 1]);
#pragma unroll
        for (int q = 0; q < 8; q++)
            ws2[16 + q] = pack2(0.5f * Wsgs[i * SD + 2 * q], 0.5f * Wsgs[i * SD + 2 * q + 1]);
        bs = 0.5f * bsgf[i];
    } else {
        const ull* pa = (const ull*)(Wsf + (size_t)(i - SD) * FD);
        const ull* pb = (const ull*)(Wss + (size_t)(i - SD) * SD);
#pragma unroll
        for (int q = 0; q < 16; q++) ws2[q] = pa[q];
#pragma unroll
        for (int q = 0; q < 8; q++) ws2[16 + q] = pb[q];
        bs = bss[i - SD];
    }
    {
        const ull* p2 = (const ull*)(Wfs + (size_t)i * SD);
#pragma unroll
        for (int q = 0; q < 8; q++) wfs2[q] = p2[q];
    }
    S->sdelta[i] = 0.f;
    S->sdr[i] = 0.f;          // sdr(0) = 0
    float hs = 0.f;           // lanes<16 meaningful
    float sdr_acc = 0.f;      // Wfs @ h_slow, register-resident
    float ssb_acc = bs;       // bias + slow-block @ h_slow accumulator
    WFENCE();

    for (int t = 0; t < T_STEPS; t++) {
        SYNC_A();                                      // h_fast(t-1) ready

        if (t > 0) {
            S->sdr[i] = sdr_acc;                       // sdr(t) (from iter t-1)
            WFENCE();
            ARRIVE_B();                                // warp0 unblocked ASAP
            // ---- all heavy work overlaps warp0's step t ----
            const float* hp = S->hfin[(t + 1) & 1];
            float hfl = hp[i];
            float sacc = dot32i(ws2, (const ulonglong2*)hp, pack2(ssb_acc, 0.f));
            float val = tanh_f(sacc);
            if (i < SD) val = fmaf(0.5f, val, 0.5f);   // sigmoid (halved domain)
            float prt = __shfl_xor_sync(0xffffffffu, val, 16);
            float delta = 0.02f * val * (prt - hs);    // lanes>=16: junk (pad)
            S->sdelta[i] = delta;
            WFENCE();
            float dsdr = dot16i(wfs2, (const ulonglong2*)S->sdelta, pack2(0.f, 0.f));
            sdr_acc += dsdr;                           // -> sdr(t+1)
            float dssb = dot16i(ws2 + 16, (const ulonglong2*)S->sdelta, pack2(0.f, 0.f));
            ssb_acc += dssb;
            if (i < SD) hs += delta;                   // exact h_slow(t-1)
            g_h[(t - 1) * HD + i] = hfl;
            if (i < SD) g_h[(t - 1) * HD + FD + i] = hs;
            if (((t & 31) == 0) && i == 0) publish(t);
        } else {
            ARRIVE_B();                                // sdr(0)=0 pre-zeroed
        }
    }

    // tail: exact slow update + row T-1
    {
        SYNC_A();
        const float* hp = S->hfin[(T_STEPS - 1) & 1];
        float sacc = dot32i(ws2, (const ulonglong2*)hp, pack2(ssb_acc, 0.f));
        float val = tanh_f(sacc);
        if (i < SD) val = fmaf(0.5f, val, 0.5f);
        float prt = __shfl_xor_sync(0xffffffffu, val, 16);
        float hsn = fmaf(0.02f * val, prt - hs, hs);
        float hfl = hp[i];
        g_h[(T_STEPS - 1) * HD + i] = hfl;
        if (i < SD) g_h[(T_STEPS - 1) * HD + FD + i] = hsn;
        __syncwarp();
        if (i == 0) publish(T_STEPS);
    }
}

// ============================================================
// head tile — one (vb, tb) partial-sumexp tile (256 threads)
// ============================================================
__device__ void head_tile(int vb, int tb,
                          const float* __restrict__ Wout,
                          const float* __restrict__ bout)
{
    int tid = threadIdx.x;
    __shared__ __align__(16) float hsh[TT][HD];
    const float* hsrc = g_h + (size_t)tb * TT * HD;
    for (int k = tid; k < TT * HD; k += 256)
        ((float*)hsh)[k] = hsrc[k];
    __syncthreads();

    float acc[TT];
#pragma unroll
    for (int q = 0; q < TT; q++) acc[q] = 0.f;

    for (int vi = 0; vi < VBLOCK / 256; vi++) {
        int v = vb * VBLOCK + vi * 256 + tid;
        if (v < VOCAB) {
            ull w2[24];
            const ulonglong2* wp = (const ulonglong2*)(Wout + (size_t)v * HD);
#pragma unroll
            for (int q = 0; q < 12; q++) {
                ulonglong2 t4 = wp[q]; w2[2 * q] = t4.x; w2[2 * q + 1] = t4.y;
            }
            ull bo2 = pack2(bout[v], 0.f);
#pragma unroll 2
            for (int tt = 0; tt < TT; tt++) {
                const ulonglong2* hp = (const ulonglong2*)hsh[tt];
                ull a0 = bo2, a1 = 0, a2 = 0, a3 = 0;
#pragma unroll
                for (int m = 0; m < 12; m++) {
                    ulonglong2 pp = hp[m];
                    if (m & 1) { FMA2(a2, w2[2 * m], pp.x); FMA2(a3, w2[2 * m + 1], pp.y); }
                    else       { FMA2(a0, w2[2 * m], pp.x); FMA2(a1, w2[2 * m + 1], pp.y); }
                }
                acc[tt] += __expf(redu4(a0, a1, a2, a3));
            }
        }
    }

    __shared__ float swarp[8][TT];
    int lane = tid & 31, wrp = tid >> 5;
#pragma unroll
    for (int tt = 0; tt < TT; tt++) {
        float v = acc[tt];
        v += __shfl_xor_sync(0xffffffff, v, 16);
        v += __shfl_xor_sync(0xffffffff, v, 8);
        v += __shfl_xor_sync(0xffffffff, v, 4);
        v += __shfl_xor_sync(0xffffffff, v, 2);
        v += __shfl_xor_sync(0xffffffff, v, 1);
        if (lane == 0) swarp[wrp][tt] = v;
    }
    __syncthreads();
    if (tid < TT) {
        float s = 0.f;
#pragma unroll
        for (int q = 0; q < 8; q++) s += swarp[q][tid];
        g_partial[(size_t)vb * T_STEPS + tb * TT + tid] = s;
    }
    __syncthreads();
}

// ============================================================
// finale — NLL + mean
// ============================================================
__device__ void finale(const int* __restrict__ tok,
                       const float* __restrict__ Wout,
                       const float* __restrict__ bout,
                       float* __restrict__ out)
{
    int tid = threadIdx.x;
    float local = 0.f;
    for (int t = tid; t < T_STEPS; t += 256) {
        float s = 0.f;
#pragma unroll
        for (int vb = 0; vb < NVB; vb++) s += g_partial[(size_t)vb * T_STEPS + t];
        int tgt = tok[t + 1];
        const float* wr = Wout + (size_t)tgt * HD;
        const float* hr = g_h + t * HD;
        float a = bout[tgt];
#pragma unroll
        for (int k = 0; k < HD; k++) a = fmaf(wr[k], hr[k], a);
        local += logf(s) - a;
    }
    __shared__ float red[256];
    red[tid] = local;
    __syncthreads();
    for (int st = 128; st > 0; st >>= 1) {
        if (tid < st) red[tid] += red[tid + st];
        __syncthreads();
    }
    if (tid == 0) out[0] = red[0] / (float)T_STEPS;
}

// ============================================================
// fused persistent kernel
// ============================================================
__global__ void __launch_bounds__(256, 1) fused_kernel(
    const int* __restrict__ tok,
    const float* __restrict__ Wgh, const float* __restrict__ bgh,
    const float* __restrict__ Wff, const float* __restrict__ bff,
    const float* __restrict__ Wfs,
    const float* __restrict__ Wsgf, const float* __restrict__ bsgf,
    const float* __restrict__ Wsgs,
    const float* __restrict__ Wss, const float* __restrict__ bss,
    const float* __restrict__ Wsf,
    const float* __restrict__ Wout, const float* __restrict__ bout,
    float* __restrict__ out)
{
    int tid = threadIdx.x;

    if (blockIdx.x == 0) {
        __shared__ __align__(16) ScanSmem S;
        int lane = tid & 31;
        if (tid < 32)
            scan_warp0(lane, &S, Wgh, bgh, Wff, bff);
        else if (tid < 64)
            scan_warp1(lane, &S, Wsgf, bsgf, Wsgs, Wss, bss, Wsf, Wfs);
        return;
    }

    __shared__ int s_tile;
    __shared__ int s_flag;
    for (;;) {
        if (tid == 0) s_tile = atomicAdd(&g_tile, 1);
        __syncthreads();
        int tile = s_tile;
        if (tile >= TILES) break;
        int tb = tile / NVB;
        int vb = tile - tb * NVB;

        if (tid == 0) {
            int need = (tb + 1) * TT;
            while (load_prog() < need) __nanosleep(64);
        }
        __syncthreads();

        head_tile(vb, tb, Wout, bout);

        if (tid == 0) {
            __threadfence();
            int d = atomicAdd(&g_done, 1);
            s_flag = (d == TILES - 1);
        }
        __syncthreads();
        if (s_flag) {
            __threadfence();
            finale(tok, Wout, bout, out);
        }
        __syncthreads();
    }
}

// ============================================================
extern "C" void kernel_launch(void* const* d_in, const int* in_sizes, int n_in,
                              void* d_out, int out_size)
{
    const int*   tok   = (const int*)  d_in[0];
    const float* embed = (const float*)d_in[1];
    const float* Wgh   = (const float*)d_in[2];
    const float* bgh   = (const float*)d_in[3];
    const float* Wgx   = (const float*)d_in[4];
    const float* Wxp   = (const float*)d_in[5];
    const float* Wff   = (const float*)d_in[6];
    const float* bff   = (const float*)d_in[7];
    const float* Wfs   = (const float*)d_in[8];
    const float* Wxf   = (const float*)d_in[9];
    const float* Wsgf  = (const float*)d_in[10];
    const float* bsgf  = (const float*)d_in[11];
    const float* Wsgs  = (const float*)d_in[12];
    const float* Wss   = (const float*)d_in[13];
    const float* bss   = (const float*)d_in[14];
    const float* Wsf   = (const float*)d_in[15];
    const float* Wout  = (const float*)d_in[16];
    const float* bout  = (const float*)d_in[17];

    precompute_kernel<<<T_STEPS, 32>>>(tok, embed, Wgx, Wxp, Wxf);
    fused_kernel<<<NBLK, 256>>>(tok, Wgh, bgh, Wff, bff, Wfs,
                                Wsgf, bsgf, Wsgs, Wss, bss, Wsf,
                                Wout, bout, (float*)d_out);
}